// round 2
// baseline (speedup 1.0000x reference)
#include <cuda_runtime.h>
#include <math.h>

// ---------------- problem constants ----------------
#define BB 8
#define TT 2048
#define VDIM 1024
#define ADIM 768
#define DM 256
#define HID 1024
#define MROWS (BB*TT)     /* 16384 */
#define XDIM (3*DM)       /* 768 */

// ---------------- device scratch (static, allocation-free) ----------------
__device__ float g_v[MROWS*DM];       // post-GEMM then post-LN video proj
__device__ float g_a[MROWS*DM];       // post-GEMM then post-LN audio proj
__device__ float g_actx[MROWS*DM];    // shifted+windowed audio context
__device__ float g_x[MROWS*XDIM];     // MLP input [an, vn, an*vn]
__device__ float g_h[MROWS*HID];      // MLP hidden (post-gelu)
__device__ float g_rnv[MROWS];        // 1/||v||
__device__ float g_rna[MROWS];        // 1/||a_ctx||

// ---------------- helpers ----------------
__device__ __forceinline__ float warp_sum(float v) {
#pragma unroll
    for (int o = 16; o > 0; o >>= 1) v += __shfl_xor_sync(0xffffffffu, v, o);
    return v;
}

__device__ __forceinline__ float gelu_exact(float x) {
    return 0.5f * x * (1.0f + erff(x * 0.70710678118654752f));
}

// ---------------- fp32 SGEMM: C[M,N] = op(A[M,K] @ B[K,N] + bias[N]) ----------------
// BM=BN=128, BK=16, 256 threads, 8x8 per-thread tile.
// M=16384 (mult of 128), N in {256,1024}, K in {1024,768} (mult of 16): no bounds checks.
template<bool GELU>
__global__ void __launch_bounds__(256) gemm_kernel(
    const float* __restrict__ A, const float* __restrict__ Bm,
    const float* __restrict__ bias, float* __restrict__ C,
    int K, int N)
{
    __shared__ float As[16][128];
    __shared__ float Bs[16][128];

    const int tid  = threadIdx.x;
    const int row0 = blockIdx.y * 128;
    const int col0 = blockIdx.x * 128;
    const int ty = tid >> 4;      // 0..15
    const int tx = tid & 15;      // 0..15

    float acc[8][8] = {};

    for (int k0 = 0; k0 < K; k0 += 16) {
        // load A tile (128x16) and B tile (16x128): 2 float4 each per thread
#pragma unroll
        for (int i = 0; i < 2; i++) {
            int l  = tid + i * 256;            // 0..511
            int ar = l >> 2;                   // 0..127
            int ac = (l & 3) << 2;             // 0,4,8,12
            float4 va = *(const float4*)&A[(size_t)(row0 + ar) * K + k0 + ac];
            As[ac + 0][ar] = va.x;
            As[ac + 1][ar] = va.y;
            As[ac + 2][ar] = va.z;
            As[ac + 3][ar] = va.w;
            int br = l >> 5;                   // 0..15
            int bc = (l & 31) << 2;            // 0..124
            *(float4*)&Bs[br][bc] = *(const float4*)&Bm[(size_t)(k0 + br) * N + col0 + bc];
        }
        __syncthreads();

#pragma unroll
        for (int kk = 0; kk < 16; kk++) {
            float a[8], b[8];
            *(float4*)&a[0] = *(float4*)&As[kk][ty * 8];
            *(float4*)&a[4] = *(float4*)&As[kk][ty * 8 + 4];
            *(float4*)&b[0] = *(float4*)&Bs[kk][tx * 8];
            *(float4*)&b[4] = *(float4*)&Bs[kk][tx * 8 + 4];
#pragma unroll
            for (int i = 0; i < 8; i++)
#pragma unroll
                for (int j = 0; j < 8; j++)
                    acc[i][j] = fmaf(a[i], b[j], acc[i][j]);
        }
        __syncthreads();
    }

    // epilogue: + bias, optional exact gelu, float4 stores
    float bcol[8];
#pragma unroll
    for (int j = 0; j < 8; j++) bcol[j] = bias[col0 + tx * 8 + j];

#pragma unroll
    for (int i = 0; i < 8; i++) {
        int r = row0 + ty * 8 + i;
        float o[8];
#pragma unroll
        for (int j = 0; j < 8; j++) {
            float c = acc[i][j] + bcol[j];
            o[j] = GELU ? gelu_exact(c) : c;
        }
        *(float4*)&C[(size_t)r * N + col0 + tx * 8]     = *(float4*)&o[0];
        *(float4*)&C[(size_t)r * N + col0 + tx * 8 + 4] = *(float4*)&o[4];
    }
}

// ---------------- LayerNorm in place over rows of 256 (warp per row) ----------------
__global__ void __launch_bounds__(256) ln_kernel(float* __restrict__ X)
{
    int row  = blockIdx.x * 8 + (threadIdx.x >> 5);
    int lane = threadIdx.x & 31;
    float* p = X + (size_t)row * DM + lane * 8;
    float4 u0 = *(const float4*)p;
    float4 u1 = *(const float4*)(p + 4);
    float s = u0.x + u0.y + u0.z + u0.w + u1.x + u1.y + u1.z + u1.w;
    s = warp_sum(s);
    float mu = s * (1.0f / DM);
    float d[8] = {u0.x-mu, u0.y-mu, u0.z-mu, u0.w-mu, u1.x-mu, u1.y-mu, u1.z-mu, u1.w-mu};
    float q = 0.f;
#pragma unroll
    for (int i = 0; i < 8; i++) q += d[i] * d[i];
    q = warp_sum(q);
    float inv = 1.0f / sqrtf(q * (1.0f / DM) + 1e-5f);
    float o[8];
#pragma unroll
    for (int i = 0; i < 8; i++) o[i] = d[i] * inv;
    *(float4*)p       = *(float4*)&o[0];
    *(float4*)(p + 4) = *(float4*)&o[4];
}

// ---------------- fractional shift + causal window average ----------------
// one thread per (row, d4) with d4 in [0,64)
__global__ void __launch_bounds__(256) shiftbox_kernel(
    const float* __restrict__ A, float* __restrict__ Out,
    const float* __restrict__ theta)
{
    int gid = blockIdx.x * 256 + threadIdx.x;
    int row = gid >> 6;
    int d4  = gid & 63;
    int b = row / TT, t = row % TT;

    float th    = fminf(fmaxf(theta[0], -12.0f), 12.0f);
    float delta = 2.0f + 4.0f / (1.0f + expf(-th));
    float dl    = fminf(fmaxf(delta, 0.0f), (float)(TT - 1));
    float nf    = floorf(dl);
    float alpha = dl - nf;
    int   ni    = (int)nf;

    float center = fminf(fmaxf((float)t + delta, 0.0f), (float)t);
    int lo = max(0, (int)ceilf(center - 5.0f));
    int hi = min(t, (int)floorf(center + 5.0f));

    const float4* Av = (const float4*)A;
    float4 acc = make_float4(0.f, 0.f, 0.f, 0.f);
    float w0 = 1.0f - alpha, w1 = alpha;
    for (int tau = lo; tau <= hi; tau++) {
        int i0 = min(max(tau - ni, 0), TT - 1);
        int i1 = min(i0 + 1, TT - 1);
        float4 x0 = Av[(size_t)(b * TT + i0) * 64 + d4];
        float4 x1 = Av[(size_t)(b * TT + i1) * 64 + d4];
        acc.x += w0 * x0.x + w1 * x1.x;
        acc.y += w0 * x0.y + w1 * x1.y;
        acc.z += w0 * x0.z + w1 * x1.z;
        acc.w += w0 * x0.w + w1 * x1.w;
    }
    float scale = 1.0f / fmaxf((float)(hi - lo + 1), 1e-8f);
    acc.x *= scale; acc.y *= scale; acc.z *= scale; acc.w *= scale;
    ((float4*)Out)[(size_t)row * 64 + d4] = acc;
}

// ---------------- reciprocal L2 norm per row (warp per row) ----------------
__global__ void __launch_bounds__(256) rnorm_kernel(
    const float* __restrict__ X, float* __restrict__ rn)
{
    int row  = blockIdx.x * 8 + (threadIdx.x >> 5);
    int lane = threadIdx.x & 31;
    const float* p = X + (size_t)row * DM + lane * 8;
    float4 u0 = *(const float4*)p;
    float4 u1 = *(const float4*)(p + 4);
    float q = u0.x*u0.x + u0.y*u0.y + u0.z*u0.z + u0.w*u0.w
            + u1.x*u1.x + u1.y*u1.y + u1.z*u1.z + u1.w*u1.w;
    q = warp_sum(q);
    if (lane == 0) rn[row] = 1.0f / fmaxf(sqrtf(q), 1e-8f);
}

// ---------------- build x = [an, vn, an*vn] ----------------
__global__ void __launch_bounds__(256) buildx_kernel(
    const float* __restrict__ Actx, const float* __restrict__ V,
    const float* __restrict__ rna, const float* __restrict__ rnv,
    float* __restrict__ X)
{
    int gid = blockIdx.x * 256 + threadIdx.x;
    int row = gid >> 6;
    int d4  = gid & 63;
    float ra = rna[row], rv = rnv[row];
    float4 a = ((const float4*)Actx)[(size_t)row * 64 + d4];
    float4 v = ((const float4*)V)[(size_t)row * 64 + d4];
    float4 an = make_float4(a.x*ra, a.y*ra, a.z*ra, a.w*ra);
    float4 vn = make_float4(v.x*rv, v.y*rv, v.z*rv, v.w*rv);
    float4 pr = make_float4(an.x*vn.x, an.y*vn.y, an.z*vn.z, an.w*vn.w);
    float4* xr = (float4*)(X + (size_t)row * XDIM);
    xr[d4]       = an;
    xr[64 + d4]  = vn;
    xr[128 + d4] = pr;
}

// ---------------- final: logit = h@W2+b2, gate, blend (warp per row) ----------------
__global__ void __launch_bounds__(256) final_kernel(
    const float* __restrict__ H, const float* __restrict__ Actx,
    const float* __restrict__ V, const float* __restrict__ W2,
    const float* __restrict__ b2, float* __restrict__ Out)
{
    int row  = blockIdx.x * 8 + (threadIdx.x >> 5);
    int lane = threadIdx.x & 31;
    const float* hr = H + (size_t)row * HID;
    float s = 0.f;
#pragma unroll
    for (int i = 0; i < 32; i++) {
        int k = i * 32 + lane;
        s = fmaf(hr[k], W2[k], s);
    }
    s = warp_sum(s);
    float logit = fminf(fmaxf(s + b2[0], -12.0f), 12.0f);
    float g = 1.0f / (1.0f + expf(-logit));
    g = fminf(fmaxf(g, 0.05f), 0.95f);
    float om = 1.0f - g;

    const float4* av = (const float4*)(Actx + (size_t)row * DM);
    const float4* vv = (const float4*)(V    + (size_t)row * DM);
    float4*       ov = (float4*)(Out + (size_t)row * DM);
#pragma unroll
    for (int j = 0; j < 2; j++) {
        int d4 = lane * 2 + j;
        float4 a = av[d4], v = vv[d4];
        ov[d4] = make_float4(g*a.x + om*v.x, g*a.y + om*v.y,
                             g*a.z + om*v.z, g*a.w + om*v.w);
    }
}

// ---------------- launch ----------------
extern "C" void kernel_launch(void* const* d_in, const int* in_sizes, int n_in,
                              void* d_out, int out_size)
{
    const float* video = (const float*)d_in[0];
    const float* audio = (const float*)d_in[1];
    const float* Wv    = (const float*)d_in[2];
    const float* bv    = (const float*)d_in[3];
    const float* Wa    = (const float*)d_in[4];
    const float* ba    = (const float*)d_in[5];
    const float* theta = (const float*)d_in[6];
    const float* W1    = (const float*)d_in[7];
    const float* b1    = (const float*)d_in[8];
    const float* W2    = (const float*)d_in[9];
    const float* b2    = (const float*)d_in[10];
    float* out = (float*)d_out;

    float *pv, *pa, *pactx, *px, *ph, *prnv, *prna;
    cudaGetSymbolAddress((void**)&pv,    g_v);
    cudaGetSymbolAddress((void**)&pa,    g_a);
    cudaGetSymbolAddress((void**)&pactx, g_actx);
    cudaGetSymbolAddress((void**)&px,    g_x);
    cudaGetSymbolAddress((void**)&ph,    g_h);
    cudaGetSymbolAddress((void**)&prnv,  g_rnv);
    cudaGetSymbolAddress((void**)&prna,  g_rna);

    // projections
    gemm_kernel<false><<<dim3(DM / 128, MROWS / 128), 256>>>(video, Wv, bv, pv, VDIM, DM);
    gemm_kernel<false><<<dim3(DM / 128, MROWS / 128), 256>>>(audio, Wa, ba, pa, ADIM, DM);
    // layernorm in place
    ln_kernel<<<MROWS / 8, 256>>>(pv);
    ln_kernel<<<MROWS / 8, 256>>>(pa);
    // fractional shift + causal box filter
    shiftbox_kernel<<<(MROWS * 64) / 256, 256>>>(pa, pactx, theta);
    // l2 norms
    rnorm_kernel<<<MROWS / 8, 256>>>(pv, prnv);
    rnorm_kernel<<<MROWS / 8, 256>>>(pactx, prna);
    // MLP input
    buildx_kernel<<<(MROWS * 64) / 256, 256>>>(pactx, pv, prna, prnv, px);
    // MLP hidden with exact gelu
    gemm_kernel<true><<<dim3(HID / 128, MROWS / 128), 256>>>(px, W1, b1, ph, XDIM, HID);
    // logits + gate + blend
    final_kernel<<<MROWS / 8, 256>>>(ph, pactx, pv, W2, b2, out);
}

// round 6
// speedup vs baseline: 1.9966x; 1.9966x over previous
#include <cuda_runtime.h>
#include <cuda_bf16.h>
#include <math.h>
#include <stdint.h>

// ---------------- problem constants ----------------
#define BB 8
#define TT 2048
#define VDIM 1024
#define ADIM 768
#define DM 256
#define HID 1024
#define MROWS (BB*TT)     /* 16384 */
#define XDIM (3*DM)       /* 768 */

// ---------------- device scratch ----------------
__device__ __align__(16) float g_v[MROWS*DM];
__device__ __align__(16) float g_a[MROWS*DM];
__device__ __align__(16) float g_actx[MROWS*DM];
__device__ __align__(16) float g_h[MROWS*HID];
__device__ float g_rnv[MROWS];
__device__ float g_rna[MROWS];
// bf16 split operands
__device__ __align__(16) __nv_bfloat16 g_vh[MROWS*VDIM];
__device__ __align__(16) __nv_bfloat16 g_vl[MROWS*VDIM];
__device__ __align__(16) __nv_bfloat16 g_auh[MROWS*ADIM];
__device__ __align__(16) __nv_bfloat16 g_aul[MROWS*ADIM];
__device__ __align__(16) __nv_bfloat16 g_xh[MROWS*XDIM];
__device__ __align__(16) __nv_bfloat16 g_xl[MROWS*XDIM];
// transposed split weights [N,K]
__device__ __align__(16) __nv_bfloat16 g_wvh[DM*VDIM],  g_wvl[DM*VDIM];
__device__ __align__(16) __nv_bfloat16 g_wah[DM*ADIM],  g_wal[DM*ADIM];
__device__ __align__(16) __nv_bfloat16 g_w1h[HID*XDIM], g_w1l[HID*XDIM];

// ---------------- helpers ----------------
__device__ __forceinline__ float warp_sum(float v) {
#pragma unroll
    for (int o = 16; o > 0; o >>= 1) v += __shfl_xor_sync(0xffffffffu, v, o);
    return v;
}
__device__ __forceinline__ float gelu_exact(float x) {
    return 0.5f * x * (1.0f + erff(x * 0.70710678118654752f));
}
__device__ __forceinline__ void split1(float x, __nv_bfloat16& h, __nv_bfloat16& l) {
    h = __float2bfloat16(x);
    l = __float2bfloat16(x - __bfloat162float(h));
}
__device__ __forceinline__ void cp_async16(uint32_t dst, const void* src) {
    asm volatile("cp.async.cg.shared.global [%0], [%1], 16;" :: "r"(dst), "l"(src));
}
__device__ __forceinline__ void cp_commit() {
    asm volatile("cp.async.commit_group;" ::: "memory");
}
template<int N> __device__ __forceinline__ void cp_wait() {
    asm volatile("cp.async.wait_group %0;" :: "n"(N) : "memory");
}
__device__ __forceinline__ uint32_t smem_u32(const void* p) {
    uint32_t a;
    asm("{ .reg .u64 t; cvta.to.shared.u64 t, %1; cvt.u32.u64 %0, t; }" : "=r"(a) : "l"(p));
    return a;
}
// mma.sync m16n8k16 bf16 (row.col), fp32 accum
__device__ __forceinline__ void mma_bf16(float* c, const uint32_t* a, const uint32_t* b) {
    asm volatile(
        "mma.sync.aligned.m16n8k16.row.col.f32.bf16.bf16.f32 "
        "{%0,%1,%2,%3}, {%4,%5,%6,%7}, {%8,%9}, {%0,%1,%2,%3};"
        : "+f"(c[0]), "+f"(c[1]), "+f"(c[2]), "+f"(c[3])
        : "r"(a[0]), "r"(a[1]), "r"(a[2]), "r"(a[3]), "r"(b[0]), "r"(b[1]));
}

// ---------------- mma.sync split-bf16 GEMM ----------------
// C[M,N] = A[M,K] @ B^T, B stored [N,K] K-major. A=Ah+Al, B=Bh+Bl.
// Accumulate AhBh + AhBl + AlBh in fp32.
// Block tile 128x128, BK=32, 8 warps (4 M x 2 N), warp tile 32x64.
#define SROW 40                       /* smem row stride in bf16 (80 bytes) */
#define OP_ELEMS (128*SROW)           /* 5120 bf16 = 10240 B per operand */
#define STAGE_ELEMS (4*OP_ELEMS)      /* 20480 bf16 = 40960 B */
#define SMEM_TOTAL_GEMM (2*STAGE_ELEMS*2)  /* 81920 B */

template<bool GELU>
__global__ void __launch_bounds__(256, 1) tc_gemm(
    const __nv_bfloat16* __restrict__ Ah, const __nv_bfloat16* __restrict__ Al,
    const __nv_bfloat16* __restrict__ Bh, const __nv_bfloat16* __restrict__ Bl,
    const float* __restrict__ bias, float* __restrict__ C, int K, int N)
{
    extern __shared__ __nv_bfloat16 smem[];
    uint32_t sbase = smem_u32(smem);
    const int tid    = threadIdx.x;
    const int wid    = tid >> 5;
    const int lane   = tid & 31;
    const int warp_m = wid >> 1;          // 0..3
    const int warp_n = wid & 1;           // 0..1
    const int lr     = lane >> 2;         // 0..7
    const int lc     = lane & 3;          // 0..3
    const int row0   = blockIdx.y * 128;
    const int col0   = blockIdx.x * 128;

    const __nv_bfloat16* Ahp = Ah + (size_t)row0 * K;
    const __nv_bfloat16* Alp = Al + (size_t)row0 * K;
    const __nv_bfloat16* Bhp = Bh + (size_t)col0 * K;
    const __nv_bfloat16* Blp = Bl + (size_t)col0 * K;

    const int nk = K >> 5;   // BK=32 iterations

    // cp.async stage loader: 128 rows x 32 cols bf16 per operand, 4x16B per row
    auto load_stage = [&](int kt, int stg) {
        uint32_t sb = sbase + stg * (STAGE_ELEMS * 2);
        int koff = kt * 32;
#pragma unroll
        for (int i = 0; i < 2; i++) {
            int id = tid + i * 256;           // 0..511
            int r  = id >> 2;                 // 0..127
            int c  = id & 3;                  // 0..3 (16B chunks)
            uint32_t soff = (uint32_t)(r * (SROW*2) + c * 16);
            size_t   goff = (size_t)r * K + koff + c * 8;
            cp_async16(sb +                    soff, Ahp + goff);
            cp_async16(sb + OP_ELEMS*2 +       soff, Alp + goff);
            cp_async16(sb + OP_ELEMS*4 +       soff, Bhp + goff);
            cp_async16(sb + OP_ELEMS*6 +       soff, Blp + goff);
        }
        cp_commit();
    };

    float acc[2][8][4];
#pragma unroll
    for (int im = 0; im < 2; im++)
#pragma unroll
        for (int in = 0; in < 8; in++)
#pragma unroll
            for (int j = 0; j < 4; j++) acc[im][in][j] = 0.f;

    load_stage(0, 0);
    for (int k = 0; k < nk; k++) {
        if (k + 1 < nk) { load_stage(k + 1, (k + 1) & 1); cp_wait<1>(); }
        else            { cp_wait<0>(); }
        __syncthreads();

        const __nv_bfloat16* sAh = smem + (size_t)(k & 1) * STAGE_ELEMS;
        const __nv_bfloat16* sAl = sAh + OP_ELEMS;
        const __nv_bfloat16* sBh = sAl + OP_ELEMS;
        const __nv_bfloat16* sBl = sBh + OP_ELEMS;

#pragma unroll
        for (int kk = 0; kk < 2; kk++) {
            int k16 = kk * 16;
            // A fragments (2 m16 tiles), hi and lo
            uint32_t aH[2][4], aL[2][4];
#pragma unroll
            for (int im = 0; im < 2; im++) {
                int r = warp_m * 32 + im * 16 + lr;
                int cofs = k16 + lc * 2;
                aH[im][0] = *(const uint32_t*)&sAh[(r    ) * SROW + cofs];
                aH[im][1] = *(const uint32_t*)&sAh[(r + 8) * SROW + cofs];
                aH[im][2] = *(const uint32_t*)&sAh[(r    ) * SROW + cofs + 8];
                aH[im][3] = *(const uint32_t*)&sAh[(r + 8) * SROW + cofs + 8];
                aL[im][0] = *(const uint32_t*)&sAl[(r    ) * SROW + cofs];
                aL[im][1] = *(const uint32_t*)&sAl[(r + 8) * SROW + cofs];
                aL[im][2] = *(const uint32_t*)&sAl[(r    ) * SROW + cofs + 8];
                aL[im][3] = *(const uint32_t*)&sAl[(r + 8) * SROW + cofs + 8];
            }
            // B fragments (8 n8 tiles), hi and lo
            uint32_t bH[8][2], bL[8][2];
#pragma unroll
            for (int in = 0; in < 8; in++) {
                int n = warp_n * 64 + in * 8 + lr;
                int cofs = k16 + lc * 2;
                bH[in][0] = *(const uint32_t*)&sBh[n * SROW + cofs];
                bH[in][1] = *(const uint32_t*)&sBh[n * SROW + cofs + 8];
                bL[in][0] = *(const uint32_t*)&sBl[n * SROW + cofs];
                bL[in][1] = *(const uint32_t*)&sBl[n * SROW + cofs + 8];
            }
            // 3-term split MMA
#pragma unroll
            for (int im = 0; im < 2; im++)
#pragma unroll
                for (int in = 0; in < 8; in++) {
                    mma_bf16(acc[im][in], aH[im], bH[in]);
                    mma_bf16(acc[im][in], aH[im], bL[in]);
                    mma_bf16(acc[im][in], aL[im], bH[in]);
                }
        }
        __syncthreads();
    }

    // epilogue: + bias, optional gelu, st.64 per fragment half
#pragma unroll
    for (int im = 0; im < 2; im++) {
        int r0 = row0 + warp_m * 32 + im * 16 + lr;
#pragma unroll
        for (int in = 0; in < 8; in++) {
            int c = col0 + warp_n * 64 + in * 8 + lc * 2;
            float b0 = bias[c], b1 = bias[c + 1];
            float2 v0, v1;
            v0.x = acc[im][in][0] + b0; v0.y = acc[im][in][1] + b1;
            v1.x = acc[im][in][2] + b0; v1.y = acc[im][in][3] + b1;
            if (GELU) {
                v0.x = gelu_exact(v0.x); v0.y = gelu_exact(v0.y);
                v1.x = gelu_exact(v1.x); v1.y = gelu_exact(v1.y);
            }
            *(float2*)&C[(size_t)(r0    ) * N + c] = v0;
            *(float2*)&C[(size_t)(r0 + 8) * N + c] = v1;
        }
    }
}

// ---------------- pre-pass: split fp32 -> bf16 hi/lo ----------------
__global__ void __launch_bounds__(256) split_kernel(
    const float* __restrict__ X, __nv_bfloat16* __restrict__ H,
    __nv_bfloat16* __restrict__ L, int n4)
{
    int i = blockIdx.x * 256 + threadIdx.x;
    if (i >= n4) return;
    float4 x = ((const float4*)X)[i];
    __nv_bfloat16 h[4], l[4];
    split1(x.x, h[0], l[0]); split1(x.y, h[1], l[1]);
    split1(x.z, h[2], l[2]); split1(x.w, h[3], l[3]);
    ((uint2*)H)[i] = *(uint2*)h;
    ((uint2*)L)[i] = *(uint2*)l;
}

// ---------------- pre-pass: transpose + split weights [K,N] -> [N,K] ----------------
__global__ void __launch_bounds__(256) wsplit_kernel(
    const float* __restrict__ W, __nv_bfloat16* __restrict__ Ht,
    __nv_bfloat16* __restrict__ Lt, int K, int N)
{
    int i = blockIdx.x * 256 + threadIdx.x;
    if (i >= K * N) return;
    int k = i / N, n = i % N;
    __nv_bfloat16 h, l;
    split1(W[i], h, l);
    Ht[(size_t)n * K + k] = h;
    Lt[(size_t)n * K + k] = l;
}

// ---------------- LayerNorm in place (warp per row of 256) ----------------
__global__ void __launch_bounds__(256) ln_kernel(float* __restrict__ X)
{
    int row  = blockIdx.x * 8 + (threadIdx.x >> 5);
    int lane = threadIdx.x & 31;
    float* p = X + (size_t)row * DM + lane * 8;
    float4 u0 = *(const float4*)p;
    float4 u1 = *(const float4*)(p + 4);
    float s = u0.x + u0.y + u0.z + u0.w + u1.x + u1.y + u1.z + u1.w;
    s = warp_sum(s);
    float mu = s * (1.0f / DM);
    float d[8] = {u0.x-mu, u0.y-mu, u0.z-mu, u0.w-mu, u1.x-mu, u1.y-mu, u1.z-mu, u1.w-mu};
    float q = 0.f;
#pragma unroll
    for (int i = 0; i < 8; i++) q += d[i] * d[i];
    q = warp_sum(q);
    float inv = 1.0f / sqrtf(q * (1.0f / DM) + 1e-5f);
    float o[8];
#pragma unroll
    for (int i = 0; i < 8; i++) o[i] = d[i] * inv;
    *(float4*)p       = *(float4*)&o[0];
    *(float4*)(p + 4) = *(float4*)&o[4];
}

// ---------------- fractional shift + causal window average ----------------
__global__ void __launch_bounds__(256) shiftbox_kernel(
    const float* __restrict__ A, float* __restrict__ Out,
    const float* __restrict__ theta)
{
    int gid = blockIdx.x * 256 + threadIdx.x;
    int row = gid >> 6;
    int d4  = gid & 63;
    int b = row / TT, t = row % TT;

    float th    = fminf(fmaxf(theta[0], -12.0f), 12.0f);
    float delta = 2.0f + 4.0f / (1.0f + expf(-th));
    float dl    = fminf(fmaxf(delta, 0.0f), (float)(TT - 1));
    float nf    = floorf(dl);
    float alpha = dl - nf;
    int   ni    = (int)nf;

    float center = fminf(fmaxf((float)t + delta, 0.0f), (float)t);
    int lo = max(0, (int)ceilf(center - 5.0f));
    int hi = min(t, (int)floorf(center + 5.0f));

    const float4* Av = (const float4*)A;
    float4 acc = make_float4(0.f, 0.f, 0.f, 0.f);
    float w0 = 1.0f - alpha, w1 = alpha;
    for (int tau = lo; tau <= hi; tau++) {
        int i0 = min(max(tau - ni, 0), TT - 1);
        int i1 = min(i0 + 1, TT - 1);
        float4 x0 = Av[(size_t)(b * TT + i0) * 64 + d4];
        float4 x1 = Av[(size_t)(b * TT + i1) * 64 + d4];
        acc.x += w0 * x0.x + w1 * x1.x;
        acc.y += w0 * x0.y + w1 * x1.y;
        acc.z += w0 * x0.z + w1 * x1.z;
        acc.w += w0 * x0.w + w1 * x1.w;
    }
    float scale = 1.0f / fmaxf((float)(hi - lo + 1), 1e-8f);
    acc.x *= scale; acc.y *= scale; acc.z *= scale; acc.w *= scale;
    ((float4*)Out)[(size_t)row * 64 + d4] = acc;
}

// ---------------- reciprocal L2 norm per row ----------------
__global__ void __launch_bounds__(256) rnorm_kernel(
    const float* __restrict__ X, float* __restrict__ rn)
{
    int row  = blockIdx.x * 8 + (threadIdx.x >> 5);
    int lane = threadIdx.x & 31;
    const float* p = X + (size_t)row * DM + lane * 8;
    float4 u0 = *(const float4*)p;
    float4 u1 = *(const float4*)(p + 4);
    float q = u0.x*u0.x + u0.y*u0.y + u0.z*u0.z + u0.w*u0.w
            + u1.x*u1.x + u1.y*u1.y + u1.z*u1.z + u1.w*u1.w;
    q = warp_sum(q);
    if (lane == 0) rn[row] = 1.0f / fmaxf(sqrtf(q), 1e-8f);
}

// ---------------- build x = [an, vn, an*vn] directly as bf16 hi/lo ----------------
__global__ void __launch_bounds__(256) buildx_kernel(
    const float* __restrict__ Actx, const float* __restrict__ V,
    const float* __restrict__ rna, const float* __restrict__ rnv,
    __nv_bfloat16* __restrict__ XH, __nv_bfloat16* __restrict__ XL)
{
    int gid = blockIdx.x * 256 + threadIdx.x;
    int row = gid >> 6;
    int d4  = gid & 63;
    float ra = rna[row], rv = rnv[row];
    float4 a = ((const float4*)Actx)[(size_t)row * 64 + d4];
    float4 v = ((const float4*)V)[(size_t)row * 64 + d4];
    float an[4] = {a.x*ra, a.y*ra, a.z*ra, a.w*ra};
    float vn[4] = {v.x*rv, v.y*rv, v.z*rv, v.w*rv};
    float pr[4] = {an[0]*vn[0], an[1]*vn[1], an[2]*vn[2], an[3]*vn[3]};

    size_t base = (size_t)row * XDIM;
    __nv_bfloat16 h[4], l[4];
#pragma unroll
    for (int i = 0; i < 4; i++) split1(an[i], h[i], l[i]);
    *(uint2*)&XH[base + 4*d4] = *(uint2*)h;
    *(uint2*)&XL[base + 4*d4] = *(uint2*)l;
#pragma unroll
    for (int i = 0; i < 4; i++) split1(vn[i], h[i], l[i]);
    *(uint2*)&XH[base + DM + 4*d4] = *(uint2*)h;
    *(uint2*)&XL[base + DM + 4*d4] = *(uint2*)l;
#pragma unroll
    for (int i = 0; i < 4; i++) split1(pr[i], h[i], l[i]);
    *(uint2*)&XH[base + 2*DM + 4*d4] = *(uint2*)h;
    *(uint2*)&XL[base + 2*DM + 4*d4] = *(uint2*)l;
}

// ---------------- final: logit = h@W2+b2, gate, blend (warp per row) ----------------
__global__ void __launch_bounds__(256) final_kernel(
    const float* __restrict__ H, const float* __restrict__ Actx,
    const float* __restrict__ V, const float* __restrict__ W2,
    const float* __restrict__ b2, float* __restrict__ Out)
{
    int row  = blockIdx.x * 8 + (threadIdx.x >> 5);
    int lane = threadIdx.x & 31;
    const float* hr = H + (size_t)row * HID;
    float s = 0.f;
#pragma unroll
    for (int i = 0; i < 32; i++) {
        int k = i * 32 + lane;
        s = fmaf(hr[k], W2[k], s);
    }
    s = warp_sum(s);
    float logit = fminf(fmaxf(s + b2[0], -12.0f), 12.0f);
    float g = 1.0f / (1.0f + expf(-logit));
    g = fminf(fmaxf(g, 0.05f), 0.95f);
    float om = 1.0f - g;

    const float4* av = (const float4*)(Actx + (size_t)row * DM);
    const float4* vv = (const float4*)(V    + (size_t)row * DM);
    float4*       ov = (float4*)(Out + (size_t)row * DM);
#pragma unroll
    for (int j = 0; j < 2; j++) {
        int d4 = lane * 2 + j;
        float4 a = av[d4], v = vv[d4];
        ov[d4] = make_float4(g*a.x + om*v.x, g*a.y + om*v.y,
                             g*a.z + om*v.z, g*a.w + om*v.w);
    }
}

// ---------------- launch ----------------
extern "C" void kernel_launch(void* const* d_in, const int* in_sizes, int n_in,
                              void* d_out, int out_size)
{
    const float* video = (const float*)d_in[0];
    const float* audio = (const float*)d_in[1];
    const float* Wv    = (const float*)d_in[2];
    const float* bv    = (const float*)d_in[3];
    const float* Wa    = (const float*)d_in[4];
    const float* ba    = (const float*)d_in[5];
    const float* theta = (const float*)d_in[6];
    const float* W1    = (const float*)d_in[7];
    const float* b1    = (const float*)d_in[8];
    const float* W2    = (const float*)d_in[9];
    const float* b2    = (const float*)d_in[10];
    float* out = (float*)d_out;

    float *pv, *pa, *pactx, *ph, *prnv, *prna;
    __nv_bfloat16 *pvh, *pvl, *pauh, *paul, *pxh, *pxl;
    __nv_bfloat16 *pwvh, *pwvl, *pwah, *pwal, *pw1h, *pw1l;
    cudaGetSymbolAddress((void**)&pv,    g_v);
    cudaGetSymbolAddress((void**)&pa,    g_a);
    cudaGetSymbolAddress((void**)&pactx, g_actx);
    cudaGetSymbolAddress((void**)&ph,    g_h);
    cudaGetSymbolAddress((void**)&prnv,  g_rnv);
    cudaGetSymbolAddress((void**)&prna,  g_rna);
    cudaGetSymbolAddress((void**)&pvh,   g_vh);
    cudaGetSymbolAddress((void**)&pvl,   g_vl);
    cudaGetSymbolAddress((void**)&pauh,  g_auh);
    cudaGetSymbolAddress((void**)&paul,  g_aul);
    cudaGetSymbolAddress((void**)&pxh,   g_xh);
    cudaGetSymbolAddress((void**)&pxl,   g_xl);
    cudaGetSymbolAddress((void**)&pwvh,  g_wvh);
    cudaGetSymbolAddress((void**)&pwvl,  g_wvl);
    cudaGetSymbolAddress((void**)&pwah,  g_wah);
    cudaGetSymbolAddress((void**)&pwal,  g_wal);
    cudaGetSymbolAddress((void**)&pw1h,  g_w1h);
    cudaGetSymbolAddress((void**)&pw1l,  g_w1l);

    cudaFuncSetAttribute(tc_gemm<false>, cudaFuncAttributeMaxDynamicSharedMemorySize, SMEM_TOTAL_GEMM);
    cudaFuncSetAttribute(tc_gemm<true>,  cudaFuncAttributeMaxDynamicSharedMemorySize, SMEM_TOTAL_GEMM);

    // pre-pass splits
    split_kernel<<<(MROWS*VDIM/4 + 255)/256, 256>>>(video, pvh, pvl, MROWS*VDIM/4);
    split_kernel<<<(MROWS*ADIM/4 + 255)/256, 256>>>(audio, pauh, paul, MROWS*ADIM/4);
    wsplit_kernel<<<(VDIM*DM + 255)/256, 256>>>(Wv, pwvh, pwvl, VDIM, DM);
    wsplit_kernel<<<(ADIM*DM + 255)/256, 256>>>(Wa, pwah, pwal, ADIM, DM);
    wsplit_kernel<<<(XDIM*HID + 255)/256, 256>>>(W1, pw1h, pw1l, XDIM, HID);

    // projections (tensor-core mma.sync)
    tc_gemm<false><<<dim3(DM/128, MROWS/128), 256, SMEM_TOTAL_GEMM>>>(
        pvh, pvl, pwvh, pwvl, bv, pv, VDIM, DM);
    tc_gemm<false><<<dim3(DM/128, MROWS/128), 256, SMEM_TOTAL_GEMM>>>(
        pauh, paul, pwah, pwal, ba, pa, ADIM, DM);

    // layernorm in place
    ln_kernel<<<MROWS/8, 256>>>(pv);
    ln_kernel<<<MROWS/8, 256>>>(pa);
    // fractional shift + causal box filter
    shiftbox_kernel<<<(MROWS*64)/256, 256>>>(pa, pactx, theta);
    // l2 norms
    rnorm_kernel<<<MROWS/8, 256>>>(pv, prnv);
    rnorm_kernel<<<MROWS/8, 256>>>(pactx, prna);
    // MLP input (split bf16)
    buildx_kernel<<<(MROWS*64)/256, 256>>>(pactx, pv, prna, prnv, pxh, pxl);
    // MLP hidden with exact gelu (tensor-core mma.sync)
    tc_gemm<true><<<dim3(HID/128, MROWS/128), 256, SMEM_TOTAL_GEMM>>>(
        pxh, pxl, pw1h, pw1l, b1, ph, XDIM, HID);
    // logits + gate + blend
    final_kernel<<<MROWS/8, 256>>>(ph, pactx, pv, W2, b2, out);
}